// round 1
// baseline (speedup 1.0000x reference)
#include <cuda_runtime.h>

// Problem constants
#define B_    16
#define CIN   512
#define COUT  256
#define H_    56
#define W_    56
#define HO    28
#define WO    28
#define NPB   (HO * WO)          // 784 spatial positions per batch after pooling
#define YTOT  (B_ * CIN * NPB)   // pooled intermediate element count

// Scratch: pooled, BN+ReLU'd intermediate y_p [B, CIN, HO, WO]  (~25.7 MB)
__device__ float g_y[YTOT];

// ---------------------------------------------------------------------------
// Kernel 1: fused inference-BN + ReLU + 2x2 avg-pool (pool commutes with the
// 1x1 conv, so we pool FIRST and shrink the GEMM by 4x).
// Pure streaming: 102.8 MB read + 25.7 MB write -> HBM bound.
// ---------------------------------------------------------------------------
__global__ void bn_relu_pool_kernel(const float* __restrict__ x,
                                    const float* __restrict__ gamma,
                                    const float* __restrict__ beta,
                                    const float* __restrict__ mean,
                                    const float* __restrict__ var) {
    int idx = blockIdx.x * blockDim.x + threadIdx.x;
    if (idx >= YTOT) return;

    int wo = idx % WO;
    int t  = idx / WO;
    int ho = t % HO;
    t /= HO;
    int c  = t % CIN;
    int b  = t / CIN;

    float sc = gamma[c] * rsqrtf(var[c] + 1e-5f);
    float sh = beta[c] - mean[c] * sc;

    const float* xp = x + (((long)(b * CIN + c) * H_ + 2 * ho) * W_ + 2 * wo);
    // 2w is even and row bases are even -> 8B aligned float2 loads
    float2 r0 = *(const float2*)xp;
    float2 r1 = *(const float2*)(xp + W_);

    float s = fmaxf(fmaf(r0.x, sc, sh), 0.f)
            + fmaxf(fmaf(r0.y, sc, sh), 0.f)
            + fmaxf(fmaf(r1.x, sc, sh), 0.f)
            + fmaxf(fmaf(r1.y, sc, sh), 0.f);
    g_y[idx] = 0.25f * s;
}

// ---------------------------------------------------------------------------
// Kernel 2: per-batch SGEMM  C[256,784] = W[256,512] * Y_b[512,784]
// BM=128, BN=64, BK=16, thread tile 8x4, 256 threads.
// Shared traffic per lane-FMA = 1.5 B < 2 B crossbar budget -> FFMA-bound.
// ---------------------------------------------------------------------------
#define BM  128
#define BN  64
#define BK  16
#define APAD 4
#define ASTR (BM + APAD)   // 132, keeps float4 alignment, halves STS conflicts

__global__ __launch_bounds__(256, 2)
void gemm_kernel(const float* __restrict__ Wmat, float* __restrict__ out) {
    __shared__ float As[BK * ASTR];  // A stored transposed: As[k][m]
    __shared__ float Bs[BK * BN];    // Bs[k][n]

    const int tid   = threadIdx.x;
    const int nBase = blockIdx.x * BN;
    const int mBase = blockIdx.y * BM;
    const int b     = blockIdx.z;

    const float* Bmat = g_y + (long)b * CIN * NPB;
    float*       Cmat = out + (long)b * COUT * NPB;

    const int tx = tid & 15;   // N direction (16 groups of 4 cols)
    const int ty = tid >> 4;   // M direction (16 groups of 8 rows)

    // A-tile load mapping: 512 float4s, 2 per thread
    const int ra0 = tid >> 2;            // rows 0..63
    const int ca0 = (tid & 3) << 2;      // k-cols {0,4,8,12}
    const int ra1 = ra0 + 64;            // rows 64..127

    // B-tile load mapping: 256 float4s, 1 per thread
    const int rb = tid >> 4;             // k-row 0..15
    const int cb = (tid & 15) << 2;      // n-col {0,4,...,60}
    const bool bvalid = (nBase + cb) < NPB;   // NPB%4==0 -> whole float4 valid

    const float4* Ag0 = (const float4*)(Wmat + (long)(mBase + ra0) * CIN + ca0);
    const float4* Ag1 = (const float4*)(Wmat + (long)(mBase + ra1) * CIN + ca0);
    const float*  Bg  = Bmat + (long)rb * NPB + nBase + cb;

    float acc[8][4];
#pragma unroll
    for (int i = 0; i < 8; i++)
#pragma unroll
        for (int j = 0; j < 4; j++) acc[i][j] = 0.f;

#pragma unroll 1
    for (int kb = 0; kb < CIN / BK; ++kb) {
        // Issue global loads early (overlap latency with other warps' compute)
        float4 a0 = Ag0[0];
        float4 a1 = Ag1[0];
        float4 bv = make_float4(0.f, 0.f, 0.f, 0.f);
        if (bvalid) bv = *(const float4*)Bg;

        __syncthreads();   // previous iteration's compute done

        As[(ca0 + 0) * ASTR + ra0] = a0.x;
        As[(ca0 + 1) * ASTR + ra0] = a0.y;
        As[(ca0 + 2) * ASTR + ra0] = a0.z;
        As[(ca0 + 3) * ASTR + ra0] = a0.w;
        As[(ca0 + 0) * ASTR + ra1] = a1.x;
        As[(ca0 + 1) * ASTR + ra1] = a1.y;
        As[(ca0 + 2) * ASTR + ra1] = a1.z;
        As[(ca0 + 3) * ASTR + ra1] = a1.w;
        *(float4*)&Bs[rb * BN + cb] = bv;

        __syncthreads();

#pragma unroll
        for (int k = 0; k < BK; k++) {
            float4 bq  = *(const float4*)&Bs[k * BN + (tx << 2)];
            float4 ap0 = *(const float4*)&As[k * ASTR + (ty << 3)];
            float4 ap1 = *(const float4*)&As[k * ASTR + (ty << 3) + 4];
            float av[8] = {ap0.x, ap0.y, ap0.z, ap0.w, ap1.x, ap1.y, ap1.z, ap1.w};
            float bw[4] = {bq.x, bq.y, bq.z, bq.w};
#pragma unroll
            for (int i = 0; i < 8; i++)
#pragma unroll
                for (int j = 0; j < 4; j++)
                    acc[i][j] = fmaf(av[i], bw[j], acc[i][j]);
        }

        Ag0 += BK / 4;
        Ag1 += BK / 4;
        Bg  += (long)BK * NPB;
    }

    const int n = nBase + (tx << 2);
    if (n < NPB) {
#pragma unroll
        for (int i = 0; i < 8; i++) {
            int m = mBase + (ty << 3) + i;
            *(float4*)&Cmat[(long)m * NPB + n] =
                make_float4(acc[i][0], acc[i][1], acc[i][2], acc[i][3]);
        }
    }
}

// ---------------------------------------------------------------------------
extern "C" void kernel_launch(void* const* d_in, const int* in_sizes, int n_in,
                              void* d_out, int out_size) {
    const float* x  = (const float*)d_in[0];
    const float* gw = (const float*)d_in[1];
    const float* gb = (const float*)d_in[2];
    const float* gm = (const float*)d_in[3];
    const float* gv = (const float*)d_in[4];
    const float* cw = (const float*)d_in[5];
    float* out = (float*)d_out;

    bn_relu_pool_kernel<<<(YTOT + 255) / 256, 256>>>(x, gw, gb, gm, gv);

    dim3 g2((NPB + BN - 1) / BN, COUT / BM, B_);   // (13, 2, 16)
    gemm_kernel<<<g2, 256>>>(cw, out);
}

// round 3
// speedup vs baseline: 2.3018x; 2.3018x over previous
#include <cuda_runtime.h>
#include <cuda_bf16.h>
#include <cstdint>

// ---------------- problem constants ----------------
#define B_    16
#define CIN   512
#define COUT  256
#define H_    56
#define W_    56
#define HO    28
#define WO    28
#define NPB   784                 // pooled positions per batch
#define NTOT  (B_ * NPB)          // 12544 GEMM columns
#define KSTK  1024                // k layout: [0,512)=hi, [512,1024)=lo

// scratch (device globals: no allocation allowed)
__device__ __align__(16) __nv_bfloat16 g_ys[(size_t)NTOT * KSTK];  // Y^T [n][k]
__device__ __align__(16) __nv_bfloat16 g_wf[COUT * KSTK];          // W split [m][k]

// ---------------- PTX helpers (baseline PTX only — no 'a' features) --------
__device__ __forceinline__ uint32_t smem_u32(const void* p) {
    uint32_t a;
    asm("{ .reg .u64 t; cvta.to.shared.u64 t, %1; cvt.u32.u64 %0, t; }" : "=r"(a) : "l"(p));
    return a;
}
#define CP_ASYNC16(dst_u32, src_ptr) \
    asm volatile("cp.async.cg.shared.global [%0], [%1], 16;" :: "r"(dst_u32), "l"(src_ptr))
#define CP_COMMIT() asm volatile("cp.async.commit_group;")
#define CP_WAIT2()  asm volatile("cp.async.wait_group 2;")

#define LDSM4(R0, R1, R2, R3, A) \
    asm volatile("ldmatrix.sync.aligned.m8n8.x4.shared.b16 {%0,%1,%2,%3}, [%4];" \
                 : "=r"(R0), "=r"(R1), "=r"(R2), "=r"(R3) : "r"(A))

#define MMA16816(C, A0, A1, A2, A3, B0, B1) \
    asm volatile("mma.sync.aligned.m16n8k16.row.col.f32.bf16.bf16.f32 " \
                 "{%0,%1,%2,%3}, {%4,%5,%6,%7}, {%8,%9}, {%0,%1,%2,%3};" \
                 : "+f"((C)[0]), "+f"((C)[1]), "+f"((C)[2]), "+f"((C)[3]) \
                 : "r"(A0), "r"(A1), "r"(A2), "r"(A3), "r"(B0), "r"(B1))

// ============================================================================
// Kernel 0: split conv weight into [m][hi(512) | lo(512)] bf16
// ============================================================================
__global__ void prep_w(const float* __restrict__ w) {
    int i = blockIdx.x * 256 + threadIdx.x;       // i < 256*512
    int m = i >> 9, c = i & 511;
    float v = w[i];
    __nv_bfloat16 hi = __float2bfloat16(v);
    __nv_bfloat16 lo = __float2bfloat16(v - __bfloat162float(hi));
    g_wf[m * KSTK + c]       = hi;
    g_wf[m * KSTK + 512 + c] = lo;
}

// ============================================================================
// Kernel 1: BN + ReLU + 2x2 avgpool + bf16 hi/lo split + transpose to [n][k]
// ============================================================================
__global__ __launch_bounds__(256) void fuse_pool(const float* __restrict__ x,
                                                 const float* __restrict__ gamma,
                                                 const float* __restrict__ beta,
                                                 const float* __restrict__ mean,
                                                 const float* __restrict__ var) {
    __shared__ __nv_bfloat16 shi[64][66];
    __shared__ __nv_bfloat16 slo[64][66];
    __shared__ float ssc[64], ssh[64];

    const int n0 = blockIdx.x * 64;
    const int c0 = blockIdx.y * 64;
    const int tid = threadIdx.x;

    if (tid < 64) {
        int c = c0 + tid;
        float sc = gamma[c] * rsqrtf(var[c] + 1e-5f);
        ssc[tid] = sc;
        ssh[tid] = beta[c] - mean[c] * sc;
    }
    __syncthreads();

    const int nl = tid & 63;
    const int n  = n0 + nl;
    const int b  = n / NPB;
    const int p  = n % NPB;
    const int ho = p / WO, wo = p % WO;
    const float* xb = x + (((long)b * CIN) * H_ + 2 * ho) * W_ + 2 * wo;
    const int cb = tid >> 6;

#pragma unroll
    for (int ci = 0; ci < 16; ci++) {
        int cl = cb * 16 + ci;
        const float* xp = xb + (long)(c0 + cl) * (H_ * W_);
        float2 r0 = *(const float2*)xp;
        float2 r1 = *(const float2*)(xp + W_);
        float sc = ssc[cl], sh = ssh[cl];
        float v = fmaxf(fmaf(r0.x, sc, sh), 0.f) + fmaxf(fmaf(r0.y, sc, sh), 0.f)
                + fmaxf(fmaf(r1.x, sc, sh), 0.f) + fmaxf(fmaf(r1.y, sc, sh), 0.f);
        v *= 0.25f;
        __nv_bfloat16 hi = __float2bfloat16(v);
        __nv_bfloat16 lo = __float2bfloat16(v - __bfloat162float(hi));
        shi[cl][nl] = hi;
        slo[cl][nl] = lo;
    }
    __syncthreads();

    const int kl = tid & 63;
    const int nb = tid >> 6;
#pragma unroll
    for (int ni = 0; ni < 16; ni++) {
        int nl2 = nb * 16 + ni;
        size_t base = (size_t)(n0 + nl2) * KSTK + c0 + kl;
        g_ys[base]       = shi[kl][nl2];
        g_ys[base + 512] = slo[kl][nl2];
    }
}

// ============================================================================
// Kernel 2: mma.sync bf16 GEMM  C[256,12544] = Whi*Yhi + Whi*Ylo + Wlo*Yhi
// CTA 128(m) x 64(n), 8 warps (32x32 each), 4-stage cp.async pipeline.
// K-chunks of 64; per chunk 4 K16 substeps; per substep per warp:
// 8 ldmatrix.x4 (Ahi,Alo x2, Bhi,Blo x2) -> 24 HMMA (3 products x 2m x 4n).
// ============================================================================
#define BM    128
#define BN    64
#define KCH   64
#define NCH   8
#define STG   4
#define A_HI  0
#define A_LO  16384
#define B_HI  32768
#define B_LO  40960
#define STAGE_B 49152
#define SMEM_TOT (STG * STAGE_B)   // 196608

__global__ __launch_bounds__(256, 1) void gemm_mma(float* __restrict__ out) {
    extern __shared__ char smem[];
    const uint32_t sb = smem_u32(smem);
    const int tid = threadIdx.x;
    const int lid = tid & 31, wid = tid >> 5;
    const int n0 = blockIdx.x * BN;
    const int m0 = blockIdx.y * BM;

    const __nv_bfloat16* Ab = g_wf + (size_t)m0 * KSTK;
    const __nv_bfloat16* Bb = g_ys + (size_t)n0 * KSTK;

    // producer mapping: 16B unit u (0..7) within 128B row, row group r0
    const int u  = tid & 7;
    const int r0 = tid >> 3;   // 0..31

    auto load_stage = [&](int j) {
        const uint32_t s = sb + (uint32_t)(j & (STG - 1)) * STAGE_B;
        const int kc = j * KCH;
#pragma unroll
        for (int jj = 0; jj < 4; jj++) {           // A: 128 rows
            int r = r0 + 32 * jj;
            uint32_t o = (uint32_t)r * 128 + (uint32_t)((u ^ (r & 7)) * 16);
            const __nv_bfloat16* a = Ab + (size_t)r * KSTK + kc + u * 8;
            CP_ASYNC16(s + A_HI + o, a);
            CP_ASYNC16(s + A_LO + o, a + 512);
        }
#pragma unroll
        for (int jj = 0; jj < 2; jj++) {           // B: 64 rows
            int r = r0 + 32 * jj;
            uint32_t o = (uint32_t)r * 128 + (uint32_t)((u ^ (r & 7)) * 16);
            const __nv_bfloat16* b = Bb + (size_t)r * KSTK + kc + u * 8;
            CP_ASYNC16(s + B_HI + o, b);
            CP_ASYNC16(s + B_LO + o, b + 512);
        }
    };

    // consumer mapping
    const int wm = wid & 3;          // 0..3 -> m offset
    const int wn = wid >> 2;         // 0..1 -> n offset
    const int mb = wm * 32;
    const int nb = wn * 32;

    // ldmatrix lane rows (fixed per lane)
    const int arow0 = mb + (lid & 15);            // A tile mt=0
    const int arow1 = arow0 + 16;                 // A tile mt=1
    const int ahalf = lid >> 4;                   // k-halves of 16B
    // B: lanes 0-7 rows 0-7 @k0 | 8-15 rows 0-7 @k8 | 16-23 rows 8-15 @k0 | 24-31 rows 8-15 @k8
    const int brow0 = nb + (lid & 7) + ((lid >> 4) << 3);   // B x4 #0 (n 0-15)
    const int brow1 = brow0 + 16;                            // B x4 #1 (n 16-31)
    const int bhalf = (lid >> 3) & 1;

    float acc[2][4][4];
#pragma unroll
    for (int i = 0; i < 2; i++)
#pragma unroll
        for (int j = 0; j < 4; j++)
#pragma unroll
            for (int k = 0; k < 4; k++) acc[i][j][k] = 0.f;

    // prologue
#pragma unroll
    for (int j = 0; j < STG - 1; j++) { load_stage(j); CP_COMMIT(); }

    for (int i = 0; i < NCH; i++) {
        CP_WAIT2();          // stage i landed (this thread)
        __syncthreads();     // all threads' stage i landed; prev stage consumed
        if (i + STG - 1 < NCH) load_stage(i + STG - 1);
        CP_COMMIT();

        const uint32_t s = sb + (uint32_t)(i & (STG - 1)) * STAGE_B;
#pragma unroll
        for (int ks = 0; ks < 4; ks++) {
            const int ua = 2 * ks + ahalf;   // 16B unit for A lanes
            const int ub = 2 * ks + bhalf;   // 16B unit for B lanes

            uint32_t a0h, a1h, a2h, a3h, a0l, a1l, a2l, a3l;  // A mt=0 hi/lo
            uint32_t a4h, a5h, a6h, a7h, a4l, a5l, a6l, a7l;  // A mt=1 hi/lo
            uint32_t b0h, b1h, b2h, b3h, b0l, b1l, b2l, b3l;  // B nt 0-1
            uint32_t b4h, b5h, b6h, b7h, b4l, b5l, b6l, b7l;  // B nt 2-3

            uint32_t aoff0 = (uint32_t)arow0 * 128 + (uint32_t)((ua ^ (arow0 & 7)) * 16);
            uint32_t aoff1 = (uint32_t)arow1 * 128 + (uint32_t)((ua ^ (arow1 & 7)) * 16);
            uint32_t boff0 = (uint32_t)brow0 * 128 + (uint32_t)((ub ^ (brow0 & 7)) * 16);
            uint32_t boff1 = (uint32_t)brow1 * 128 + (uint32_t)((ub ^ (brow1 & 7)) * 16);

            LDSM4(a0h, a1h, a2h, a3h, s + A_HI + aoff0);
            LDSM4(a4h, a5h, a6h, a7h, s + A_HI + aoff1);
            LDSM4(a0l, a1l, a2l, a3l, s + A_LO + aoff0);
            LDSM4(a4l, a5l, a6l, a7l, s + A_LO + aoff1);
            LDSM4(b0h, b1h, b2h, b3h, s + B_HI + boff0);
            LDSM4(b4h, b5h, b6h, b7h, s + B_HI + boff1);
            LDSM4(b0l, b1l, b2l, b3l, s + B_LO + boff0);
            LDSM4(b4l, b5l, b6l, b7l, s + B_LO + boff1);

            // product 1: Ahi * Bhi
            MMA16816(acc[0][0], a0h, a1h, a2h, a3h, b0h, b1h);
            MMA16816(acc[0][1], a0h, a1h, a2h, a3h, b2h, b3h);
            MMA16816(acc[0][2], a0h, a1h, a2h, a3h, b4h, b5h);
            MMA16816(acc[0][3], a0h, a1h, a2h, a3h, b6h, b7h);
            MMA16816(acc[1][0], a4h, a5h, a6h, a7h, b0h, b1h);
            MMA16816(acc[1][1], a4h, a5h, a6h, a7h, b2h, b3h);
            MMA16816(acc[1][2], a4h, a5h, a6h, a7h, b4h, b5h);
            MMA16816(acc[1][3], a4h, a5h, a6h, a7h, b6h, b7h);
            // product 2: Ahi * Blo
            MMA16816(acc[0][0], a0h, a1h, a2h, a3h, b0l, b1l);
            MMA16816(acc[0][1], a0h, a1h, a2h, a3h, b2l, b3l);
            MMA16816(acc[0][2], a0h, a1h, a2h, a3h, b4l, b5l);
            MMA16816(acc[0][3], a0h, a1h, a2h, a3h, b6l, b7l);
            MMA16816(acc[1][0], a4h, a5h, a6h, a7h, b0l, b1l);
            MMA16816(acc[1][1], a4h, a5h, a6h, a7h, b2l, b3l);
            MMA16816(acc[1][2], a4h, a5h, a6h, a7h, b4l, b5l);
            MMA16816(acc[1][3], a4h, a5h, a6h, a7h, b6l, b7l);
            // product 3: Alo * Bhi
            MMA16816(acc[0][0], a0l, a1l, a2l, a3l, b0h, b1h);
            MMA16816(acc[0][1], a0l, a1l, a2l, a3l, b2h, b3h);
            MMA16816(acc[0][2], a0l, a1l, a2l, a3l, b4h, b5h);
            MMA16816(acc[0][3], a0l, a1l, a2l, a3l, b6h, b7h);
            MMA16816(acc[1][0], a4l, a5l, a6l, a7l, b0h, b1h);
            MMA16816(acc[1][1], a4l, a5l, a6l, a7l, b2h, b3h);
            MMA16816(acc[1][2], a4l, a5l, a6l, a7l, b4h, b5h);
            MMA16816(acc[1][3], a4l, a5l, a6l, a7l, b6h, b7h);
        }
    }

    // epilogue: direct float2 stores (n-pairs never straddle a batch: NPB even)
#pragma unroll
    for (int mt = 0; mt < 2; mt++) {
#pragma unroll
        for (int nt = 0; nt < 4; nt++) {
            int m  = m0 + mb + mt * 16 + (lid >> 2);
            int nn = n0 + nb + nt * 8 + (lid & 3) * 2;
            int bb = nn / NPB, p = nn % NPB;
            float* o0 = out + ((size_t)bb * COUT + m) * NPB + p;
            *(float2*)o0 = make_float2(acc[mt][nt][0], acc[mt][nt][1]);
            *(float2*)(o0 + 8 * NPB) = make_float2(acc[mt][nt][2], acc[mt][nt][3]);
        }
    }
}

// ============================================================================
extern "C" void kernel_launch(void* const* d_in, const int* in_sizes, int n_in,
                              void* d_out, int out_size) {
    const float* x  = (const float*)d_in[0];
    const float* gw = (const float*)d_in[1];
    const float* gb = (const float*)d_in[2];
    const float* gm = (const float*)d_in[3];
    const float* gv = (const float*)d_in[4];
    const float* cw = (const float*)d_in[5];
    float* out = (float*)d_out;

    cudaFuncSetAttribute(gemm_mma, cudaFuncAttributeMaxDynamicSharedMemorySize, SMEM_TOT);

    prep_w<<<(COUT * CIN) / 256, 256>>>(cw);
    fuse_pool<<<dim3(NTOT / 64, CIN / 64), 256>>>(x, gw, gb, gm, gv);
    gemm_mma<<<dim3(NTOT / BN, COUT / BM), 256, SMEM_TOT>>>(out);
}